// round 17
// baseline (speedup 1.0000x reference)
#include <cuda_runtime.h>
#include <cstdint>

// Problem constants
#define Bx 2
#define Tx 2048
#define Cx 1024
#define Hx 16
#define Dx 64
#define Mrows (Bx*Tx)   // 4096

// Scratch in __device__ globals (no allocations allowed)
__device__ float g_q[(size_t)Bx*Hx*Tx*Dx];    // [B,H,T,D] (tf32-rounded)
__device__ float g_k[(size_t)Bx*Hx*Tx*Dx];
__device__ float g_v[(size_t)Bx*Hx*Tx*Dx];
__device__ float g_y[(size_t)Mrows*Cx];       // [B*T, C]  (tf32-rounded)
__device__ float g_xr[(size_t)Mrows*Cx];      // tf32-rounded X
__device__ float g_wr4[4][(size_t)Cx*Cx];     // tf32-rounded Wq,Wk,Wv,Wp

__device__ __forceinline__ uint32_t smem_u32(const void* p) {
    uint32_t a;
    asm("{ .reg .u64 t; cvta.to.shared.u64 t, %1; cvt.u32.u64 %0, t; }" : "=r"(a) : "l"(p));
    return a;
}
__device__ __forceinline__ uint32_t f2tf32(float f) {
    uint32_t u;
    asm("cvt.rna.tf32.f32 %0, %1;" : "=r"(u) : "f"(f));
    return u;
}
__device__ __forceinline__ void ldsm_x4(uint32_t* r, uint32_t addr) {
    asm volatile("ldmatrix.sync.aligned.m8n8.x4.shared.b16 {%0,%1,%2,%3}, [%4];"
        : "=r"(r[0]), "=r"(r[1]), "=r"(r[2]), "=r"(r[3]) : "r"(addr));
}
#define MMA_TF32(C, A0,A1,A2,A3, B0,B1) \
    asm volatile("mma.sync.aligned.m16n8k8.row.col.f32.tf32.tf32.f32 " \
        "{%0,%1,%2,%3}, {%4,%5,%6,%7}, {%8,%9}, {%0,%1,%2,%3};" \
        : "+f"((C)[0]), "+f"((C)[1]), "+f"((C)[2]), "+f"((C)[3]) \
        : "r"(A0), "r"(A1), "r"(A2), "r"(A3), "r"(B0), "r"(B1))

// ---------------------------------------------------------------------------
// Fused tf32 rounding pre-pass: X (4M elems) + 4 weights (1M each).
// ---------------------------------------------------------------------------
__global__ __launch_bounds__(256) void round_all_kernel(
    const float* __restrict__ x,
    const float* __restrict__ wq, const float* __restrict__ wk,
    const float* __restrict__ wv, const float* __restrict__ wp,
    float* __restrict__ xr, float* __restrict__ wr)
{
    int bid = blockIdx.x;
    const float* src;
    float* dst;
    int off;
    if (bid < 4096) {
        src = x; dst = xr; off = bid * 1024;
    } else {
        int seg = (bid - 4096) >> 10;
        off = ((bid - 4096) & 1023) * 1024;
        src = (seg == 0) ? wq : (seg == 1) ? wk : (seg == 2) ? wv : wp;
        dst = wr + (size_t)seg * Cx * Cx;
    }
    int i = off + threadIdx.x * 4;
    float4 v = *(const float4*)(src + i);
    float4 o;
    o.x = __uint_as_float(f2tf32(v.x));
    o.y = __uint_as_float(f2tf32(v.y));
    o.z = __uint_as_float(f2tf32(v.z));
    o.w = __uint_as_float(f2tf32(v.w));
    *(float4*)(dst + i) = o;
}

// ---------------------------------------------------------------------------
// tf32 mma.sync GEMM (inputs pre-rounded; ldmatrix x4 frags for A and B;
// 1 barrier/k-iter; cp.async issued after first frag loads).
// CTA 128x128, BK=32, 8 warps (2x4) x 64x32, 3-stage.
// grid.z selects (W, bias, out) set for fused QKV.
// ---------------------------------------------------------------------------
__global__ __launch_bounds__(256, 2) void mma_gemm(
    const float* __restrict__ X,
    const float* __restrict__ Wa, const float* __restrict__ Wb2,
    const float* __restrict__ Wc,
    const float* __restrict__ ba, const float* __restrict__ bb2,
    const float* __restrict__ bc,
    float* __restrict__ oa, float* __restrict__ ob2, float* __restrict__ oc,
    int split, int round_out)
{
    constexpr int NK = 32;
    constexpr uint32_t LDB = 144u;     // 36 floats row stride (bytes)
    constexpr uint32_t STB = 36864u;   // per stage: A 18432 + B 18432
    extern __shared__ float smf[];
    const uint32_t sb = smem_u32(smf);

    const int z = blockIdx.z;
    const float* W    = (z == 0) ? Wa : (z == 1) ? Wb2 : Wc;
    const float* bias = (z == 0) ? ba : (z == 1) ? bb2 : bc;
    float* out        = (z == 0) ? oa : (z == 1) ? ob2 : oc;

    const int tid = threadIdx.x;
    const int wid = tid >> 5, lane = tid & 31;
    const int wm = wid >> 2, wn = wid & 3;
    const int bm = blockIdx.y * 128, bn = blockIdx.x * 128;

    const float* Xb = X + (size_t)bm * 1024;
    const float* Wb = W + (size_t)bn * 1024;

    const uint32_t aOff = (uint32_t)(lane & 15) * LDB + ((lane >> 4) & 1) * 16u;
    const uint32_t bOff4 = (uint32_t)(lane & 7) * LDB + ((lane >> 3) & 1) * 16u
                         + ((lane >> 4) & 1) * (8u * LDB);

    float acc[4][4][4];
#pragma unroll
    for (int mt = 0; mt < 4; mt++)
#pragma unroll
        for (int nt = 0; nt < 4; nt++)
#pragma unroll
            for (int r = 0; r < 4; r++) acc[mt][nt][r] = 0.0f;

    auto load_stage = [&](int s, int kc) {
        uint32_t A = sb + (uint32_t)s * STB;
        uint32_t B = A + 18432u;
        const float* xs = Xb + kc * 32;
        const float* ws = Wb + kc * 32;
#pragma unroll
        for (int i = 0; i < 4; i++) {
            int f = tid + i * 256;
            int r = f >> 3;
            int c4 = (f & 7) * 4;
            uint32_t off = (uint32_t)r * LDB + (uint32_t)c4 * 4u;
            asm volatile("cp.async.cg.shared.global [%0], [%1], 16;"
                         :: "r"(A + off), "l"(xs + (size_t)r * 1024 + c4) : "memory");
            asm volatile("cp.async.cg.shared.global [%0], [%1], 16;"
                         :: "r"(B + off), "l"(ws + (size_t)r * 1024 + c4) : "memory");
        }
        asm volatile("cp.async.commit_group;" ::: "memory");
    };

    load_stage(0, 0);
    load_stage(1, 1);

    for (int k = 0; k < NK; k++) {
        if (k + 1 < NK)
            asm volatile("cp.async.wait_group 1;" ::: "memory");
        else
            asm volatile("cp.async.wait_group 0;" ::: "memory");
        __syncthreads();

        const uint32_t As = sb + (uint32_t)(k % 3) * STB;
        const uint32_t Bs = As + 18432u;
        const uint32_t aBase = As + (uint32_t)(wm * 64) * LDB + aOff;
        const uint32_t bBase = Bs + (uint32_t)(wn * 32) * LDB + bOff4;

#pragma unroll
        for (int kk = 0; kk < 4; kk++) {
            uint32_t af[4][4], bf[2][4];
#pragma unroll
            for (int mt = 0; mt < 4; mt++)
                ldsm_x4(af[mt], aBase + (uint32_t)(mt * 16) * LDB + kk * 32u);
#pragma unroll
            for (int np = 0; np < 2; np++)
                ldsm_x4(bf[np], bBase + (uint32_t)(np * 16) * LDB + kk * 32u);
            // Issue next-stage cp.async AFTER the first frag loads so the
            // post-barrier LSU burst doesn't delay the LDSM->MMA chain.
            if (kk == 0 && k + 2 < NK) load_stage((k + 2) % 3, k + 2);
#pragma unroll
            for (int mt = 0; mt < 4; mt++)
#pragma unroll
                for (int nt = 0; nt < 4; nt++)
                    MMA_TF32(acc[mt][nt], af[mt][0], af[mt][1], af[mt][2], af[mt][3],
                             bf[nt >> 1][(nt & 1) * 2], bf[nt >> 1][(nt & 1) * 2 + 1]);
        }
    }

    const int lr = lane >> 2, lc = lane & 3;
#pragma unroll
    for (int mt = 0; mt < 4; mt++) {
#pragma unroll
        for (int nt = 0; nt < 4; nt++) {
            int row = bm + wm * 64 + mt * 16 + lr;
            int col = bn + wn * 32 + nt * 8 + lc * 2;
            float b0 = __ldg(bias + col), b1 = __ldg(bias + col + 1);
            float2 v0 = make_float2(acc[mt][nt][0] + b0, acc[mt][nt][1] + b1);
            float2 v1 = make_float2(acc[mt][nt][2] + b0, acc[mt][nt][3] + b1);
            if (round_out) {
                v0.x = __uint_as_float(f2tf32(v0.x));
                v0.y = __uint_as_float(f2tf32(v0.y));
                v1.x = __uint_as_float(f2tf32(v1.x));
                v1.y = __uint_as_float(f2tf32(v1.y));
            }
            if (split) {
                int h_ = col >> 6, d_ = col & 63;
                int b_ = row >> 11, t_ = row & 2047;
                size_t base = (((size_t)(b_ * Hx + h_) * Tx) + t_) * Dx + d_;
                *(float2*)(out + base) = v0;
                int t2 = (row + 8) & 2047;
                size_t base2 = (((size_t)(b_ * Hx + h_) * Tx) + t2) * Dx + d_;
                *(float2*)(out + base2) = v1;
            } else {
                *(float2*)(out + (size_t)row * Cx + col) = v0;
                *(float2*)(out + (size_t)(row + 8) * Cx + col) = v1;
            }
        }
    }
}

// ---------------------------------------------------------------------------
// Tensor-core flash attention (tf32 mma.sync), 2 CTAs/SM.
// CTA = 128 q-rows, 8 warps x 16 rows. K-tiles of 128 processed in FOUR
// 32-key chunks (s[4][4] keeps regs < 128 so two CTAs co-reside; one CTA's
// K/V fill latency is hidden by the other CTA's compute).
// ldmatrix x4 Q + paired-K frags, shuffle-transpose P, single K/V buffer.
// ---------------------------------------------------------------------------
__global__ __launch_bounds__(256, 2) void attn_mma(
    const float* __restrict__ q, const float* __restrict__ k,
    const float* __restrict__ v, float* __restrict__ y)
{
    constexpr int QP = 68, KP = 68, VP = 72;
    constexpr uint32_t QPB = QP * 4, KPB = KP * 4, VPB = VP * 4;
    extern __shared__ uint32_t sw[];
    uint32_t* Qs = sw;                 // 128*QP
    uint32_t* Ks = Qs + 128 * QP;      // 128*KP
    uint32_t* Vs = Ks + 128 * KP;      // 128*VP  -> 106496 bytes

    const int bh = blockIdx.y;
    const int qt = gridDim.x - 1 - blockIdx.x;   // heaviest tiles first
    const int q0 = qt * 128;
    const int tid = threadIdx.x;
    const int wid = tid >> 5, lane = tid & 31;
    const int lr = lane >> 2, lc = lane & 3;
    const float* qb = q + (size_t)bh * Tx * Dx;
    const float* kb = k + (size_t)bh * Tx * Dx;
    const float* vb = v + (size_t)bh * Tx * Dx;

    const uint32_t sQ = smem_u32(Qs), sK = smem_u32(Ks), sV = smem_u32(Vs);
    const uint32_t qOff = (uint32_t)(lane & 15) * QPB + ((lane >> 4) & 1) * 16u
                        + (uint32_t)(wid * 16) * QPB;
    const uint32_t kOff4 = (uint32_t)(lane & 7) * KPB + ((lane >> 3) & 1) * 16u
                         + ((lane >> 4) & 1) * (8u * KPB);

    // Load Q tile: raw copy with 1/8 scale folded (exact on tf32 values)
#pragma unroll
    for (int l = 0; l < 8; l++) {
        int f = tid + l * 256;
        int r = f >> 4, c4 = (f & 15) * 4;
        float4 t = *(const float4*)&qb[(size_t)(q0 + r) * Dx + c4];
        t.x *= 0.125f; t.y *= 0.125f; t.z *= 0.125f; t.w *= 0.125f;
        *(float4*)&Qs[r * QP + c4] = t;
    }

    float m0 = -1e30f, m1 = -1e30f, l0 = 0.0f, l1 = 0.0f;
    float o[8][4];
#pragma unroll
    for (int dn = 0; dn < 8; dn++)
#pragma unroll
        for (int r = 0; r < 4; r++) o[dn][r] = 0.0f;

    const uint32_t srcA = (lane & ~3) | (lc >> 1);
    const uint32_t srcB = srcA + 2;

    for (int jb = 0; jb <= qt; jb++) {
        const int j0 = jb * 128;
        __syncthreads();               // prior iter done reading Ks/Vs
        // K/V fill via cp.async (other co-resident CTA hides this latency)
#pragma unroll
        for (int l = 0; l < 8; l++) {
            int f = tid + l * 256;
            int r = f >> 4;
            uint32_t cb = (uint32_t)(f & 15) * 16u;
            const char* kg = (const char*)&kb[(size_t)(j0 + r) * Dx] + cb;
            const char* vg = (const char*)&vb[(size_t)(j0 + r) * Dx] + cb;
            asm volatile("cp.async.cg.shared.global [%0], [%1], 16;"
                         :: "r"(sK + (uint32_t)r * KPB + cb), "l"(kg) : "memory");
            asm volatile("cp.async.cg.shared.global [%0], [%1], 16;"
                         :: "r"(sV + (uint32_t)r * VPB + cb), "l"(vg) : "memory");
        }
        asm volatile("cp.async.commit_group;" ::: "memory");
        asm volatile("cp.async.wait_group 0;" ::: "memory");
        __syncthreads();

#pragma unroll
        for (int cc = 0; cc < 4; cc++) {
            const int kb0 = cc * 32;
            // Diagonal tile: skip chunks fully above this warp's rows
            if (jb == qt && kb0 >= wid * 16 + 16) continue;

            // S = Q @ K^T for this 32-key chunk (4 n-tiles)
            float s[4][4];
#pragma unroll
            for (int nt = 0; nt < 4; nt++)
#pragma unroll
                for (int r = 0; r < 4; r++) s[nt][r] = 0.0f;

#pragma unroll
            for (int ks = 0; ks < 8; ks++) {
                uint32_t af[4];
                ldsm_x4(af, sQ + qOff + ks * 32u);
#pragma unroll
                for (int np = 0; np < 2; np++) {
                    uint32_t bf[4];
                    ldsm_x4(bf, sK + (uint32_t)(kb0 + np * 16) * KPB + kOff4 + ks * 32u);
                    MMA_TF32(s[np * 2],     af[0], af[1], af[2], af[3], bf[0], bf[1]);
                    MMA_TF32(s[np * 2 + 1], af[0], af[1], af[2], af[3], bf[2], bf[3]);
                }
            }

            // Causal mask (diagonal tile only)
            if (jb == qt) {
                int r0g = q0 + wid * 16 + lr;
                int r1g = r0g + 8;
#pragma unroll
                for (int nt = 0; nt < 4; nt++) {
                    int c0g = j0 + kb0 + nt * 8 + lc * 2;
                    if (c0g > r0g)     s[nt][0] = -1e30f;
                    if (c0g + 1 > r0g) s[nt][1] = -1e30f;
                    if (c0g > r1g)     s[nt][2] = -1e30f;
                    if (c0g + 1 > r1g) s[nt][3] = -1e30f;
                }
            }

            // Online softmax for the chunk
            float tm0 = -1e30f, tm1 = -1e30f;
#pragma unroll
            for (int nt = 0; nt < 4; nt++) {
                tm0 = fmaxf(tm0, fmaxf(s[nt][0], s[nt][1]));
                tm1 = fmaxf(tm1, fmaxf(s[nt][2], s[nt][3]));
            }
            tm0 = fmaxf(tm0, __shfl_xor_sync(0xffffffffu, tm0, 1));
            tm0 = fmaxf(tm0, __shfl_xor_sync(0xffffffffu, tm0, 2));
            tm1 = fmaxf(tm1, __shfl_xor_sync(0xffffffffu, tm1, 1));
            tm1 = fmaxf(tm1, __shfl_xor_sync(0xffffffffu, tm1, 2));

            float mn0 = fmaxf(m0, tm0), mn1 = fmaxf(m1, tm1);
            float f0 = __expf(m0 - mn0), f1 = __expf(m1 - mn1);
            float su0 = 0.0f, su1 = 0.0f;
#pragma unroll
            for (int nt = 0; nt < 4; nt++) {
                float p0 = __expf(s[nt][0] - mn0);
                float p1 = __expf(s[nt][1] - mn0);
                float p2 = __expf(s[nt][2] - mn1);
                float p3 = __expf(s[nt][3] - mn1);
                su0 += p0 + p1;
                su1 += p2 + p3;
                s[nt][0] = __uint_as_float(f2tf32(p0));
                s[nt][1] = __uint_as_float(f2tf32(p1));
                s[nt][2] = __uint_as_float(f2tf32(p2));
                s[nt][3] = __uint_as_float(f2tf32(p3));
            }
            su0 += __shfl_xor_sync(0xffffffffu, su0, 1);
            su0 += __shfl_xor_sync(0xffffffffu, su0, 2);
            su1 += __shfl_xor_sync(0xffffffffu, su1, 1);
            su1 += __shfl_xor_sync(0xffffffffu, su1, 2);

            l0 = l0 * f0 + su0;
            l1 = l1 * f1 + su1;
            m0 = mn0; m1 = mn1;
#pragma unroll
            for (int dn = 0; dn < 8; dn++) {
                o[dn][0] *= f0; o[dn][1] *= f0;
                o[dn][2] *= f1; o[dn][3] *= f1;
            }

            // O += P @ V : shuffle-transpose S accum -> A fragments (per quad)
#pragma unroll
            for (int nt = 0; nt < 4; nt++) {
                float u0 = __shfl_sync(0xffffffffu, s[nt][0], srcA);
                float u1 = __shfl_sync(0xffffffffu, s[nt][1], srcA);
                float u2 = __shfl_sync(0xffffffffu, s[nt][2], srcA);
                float u3 = __shfl_sync(0xffffffffu, s[nt][3], srcA);
                float w0 = __shfl_sync(0xffffffffu, s[nt][0], srcB);
                float w1 = __shfl_sync(0xffffffffu, s[nt][1], srcB);
                float w2 = __shfl_sync(0xffffffffu, s[nt][2], srcB);
                float w3 = __shfl_sync(0xffffffffu, s[nt][3], srcB);
                bool odd = (lc & 1);
                uint32_t a0 = __float_as_uint(odd ? u1 : u0);
                uint32_t a1 = __float_as_uint(odd ? u3 : u2);
                uint32_t a2 = __float_as_uint(odd ? w1 : w0);
                uint32_t a3 = __float_as_uint(odd ? w3 : w2);
                const int kr = kb0 + nt * 8;
#pragma unroll
                for (int dn = 0; dn < 8; dn++) {
                    uint32_t b0 = Vs[(kr + lc) * VP + dn * 8 + lr];
                    uint32_t b1 = Vs[(kr + lc + 4) * VP + dn * 8 + lr];
                    MMA_TF32(o[dn], a0, a1, a2, a3, b0, b1);
                }
            }
        }
    }

    // Epilogue: y[B,T,C], rounded to tf32 for the final GEMM
    const int b_ = bh >> 4, h_ = bh & 15;
    const float i0 = 1.0f / l0, i1 = 1.0f / l1;
    const int r0g = q0 + wid * 16 + lr;
#pragma unroll
    for (int dn = 0; dn < 8; dn++) {
        int col = h_ * Dx + dn * 8 + lc * 2;
        float2 w0, w1;
        w0.x = __uint_as_float(f2tf32(o[dn][0] * i0));
        w0.y = __uint_as_float(f2tf32(o[dn][1] * i0));
        w1.x = __uint_as_float(f2tf32(o[dn][2] * i1));
        w1.y = __uint_as_float(f2tf32(o[dn][3] * i1));
        *(float2*)&y[((size_t)b_ * Tx + r0g) * Cx + col] = w0;
        *(float2*)&y[((size_t)b_ * Tx + r0g + 8) * Cx + col] = w1;
    }
}

// ---------------------------------------------------------------------------
extern "C" void kernel_launch(void* const* d_in, const int* in_sizes, int n_in,
                              void* d_out, int out_size)
{
    const float* x  = (const float*)d_in[0];
    // d_in[1] = att_mask (causal tril) — handled structurally in-kernel
    const float* wq = (const float*)d_in[2];
    const float* bq = (const float*)d_in[3];
    const float* wk = (const float*)d_in[4];
    const float* bk = (const float*)d_in[5];
    const float* wv = (const float*)d_in[6];
    const float* bv = (const float*)d_in[7];
    const float* wp = (const float*)d_in[8];
    const float* bp = (const float*)d_in[9];
    float* out = (float*)d_out;

    float *qp, *kp, *vp, *yp, *xr, *wr;
    cudaGetSymbolAddress((void**)&qp, g_q);
    cudaGetSymbolAddress((void**)&kp, g_k);
    cudaGetSymbolAddress((void**)&vp, g_v);
    cudaGetSymbolAddress((void**)&yp, g_y);
    cudaGetSymbolAddress((void**)&xr, g_xr);
    cudaGetSymbolAddress((void**)&wr, g_wr4);

    const int gemm_smem = 3 * 36864;   // 110592 (3 stages)
    cudaFuncSetAttribute(mma_gemm, cudaFuncAttributeMaxDynamicSharedMemorySize, gemm_smem);

    // Pre-round X + all weights to tf32 (one launch)
    round_all_kernel<<<4096 + 4 * 1024, 256>>>(x, wq, wk, wv, wp, xr, wr);

    // Fused QKV projection: grid.z selects W/bias/out
    mma_gemm<<<dim3(8, 32, 3), 256, gemm_smem>>>(
        xr, wr, wr + (size_t)Cx * Cx, wr + 2 * (size_t)Cx * Cx,
        bq, bk, bv, qp, kp, vp, 1, 1);

    // attn smem: Q 34816 + K 34816 + V 36864 = 106496 (2 CTAs/SM)
    const int attn_smem = 128 * (68 + 68 + 72) * 4;
    cudaFuncSetAttribute(attn_mma, cudaFuncAttributeMaxDynamicSharedMemorySize, attn_smem);
    attn_mma<<<dim3(Tx / 128, Bx * Hx), 256, attn_smem>>>(qp, kp, vp, yp);

    // Output projection (y tf32-rounded by attn epilogue)
    mma_gemm<<<dim3(8, 32, 1), 256, gemm_smem>>>(
        yp, wr + 3 * (size_t)Cx * Cx, nullptr, nullptr,
        bp, nullptr, nullptr, out, nullptr, nullptr, 0, 0);
}